// round 9
// baseline (speedup 1.0000x reference)
#include <cuda_runtime.h>
#include <cstdint>

#define EPS 1e-06f
#define MAX_V 2000000

#define FP_SCALE   65536.0
#define COUNT_ONE  (1ULL << 48)
#define SUM_MASK   (COUNT_ONE - 1ULL)

__device__ float4 g_x4[MAX_V];
__device__ unsigned long long g_packed_acc;
__device__ double g_energy_acc;   // fallback path only

__global__ void __launch_bounds__(256)
repack_kernel(const float* __restrict__ x, int V)
{
    int v = blockIdx.x * blockDim.x + threadIdx.x;
    if (v == 0) {
        g_packed_acc = 0ULL;
        g_energy_acc = 0.0;
    }
    if (v < V) {
        float a = __ldg(x + 3 * v + 0);
        float b = __ldg(x + 3 * v + 1);
        float c = __ldg(x + 3 * v + 2);
        g_x4[v] = make_float4(a, b, c, 0.0f);
    }
}

// 8 edges per thread: 16 front-batched gathers for max in-flight MLP.
__global__ void __launch_bounds__(256)
spring_energy_kernel(const int* __restrict__ indices,  // [E*2] int32
                     const float* __restrict__ l0,
                     const float* __restrict__ k,
                     long long E,
                     float* __restrict__ out)
{
    long long t    = (long long)blockIdx.x * blockDim.x + threadIdx.x;
    long long base = 8 * t;

    float term = 0.0f;
    if (base + 7 < E) {
        // 4 x int4 = 8 edges' indices (64B/thread, coalesced)
        int4 p0 = __ldg((const int4*)(indices + 2 * base) + 0);
        int4 p1 = __ldg((const int4*)(indices + 2 * base) + 1);
        int4 p2 = __ldg((const int4*)(indices + 2 * base) + 2);
        int4 p3 = __ldg((const int4*)(indices + 2 * base) + 3);
        float4 l0a = __ldg((const float4*)(l0 + base) + 0);
        float4 l0b = __ldg((const float4*)(l0 + base) + 1);
        float4 ka  = __ldg((const float4*)(k  + base) + 0);
        float4 kb  = __ldg((const float4*)(k  + base) + 1);

        // Front-batch all 16 gathers.
        float4 va[8], vb[8];
        va[0] = __ldg(&g_x4[p0.x]); vb[0] = __ldg(&g_x4[p0.y]);
        va[1] = __ldg(&g_x4[p0.z]); vb[1] = __ldg(&g_x4[p0.w]);
        va[2] = __ldg(&g_x4[p1.x]); vb[2] = __ldg(&g_x4[p1.y]);
        va[3] = __ldg(&g_x4[p1.z]); vb[3] = __ldg(&g_x4[p1.w]);
        va[4] = __ldg(&g_x4[p2.x]); vb[4] = __ldg(&g_x4[p2.y]);
        va[5] = __ldg(&g_x4[p2.z]); vb[5] = __ldg(&g_x4[p2.w]);
        va[6] = __ldg(&g_x4[p3.x]); vb[6] = __ldg(&g_x4[p3.y]);
        va[7] = __ldg(&g_x4[p3.z]); vb[7] = __ldg(&g_x4[p3.w]);

        float l0v[8] = {l0a.x, l0a.y, l0a.z, l0a.w, l0b.x, l0b.y, l0b.z, l0b.w};
        float kv[8]  = {ka.x,  ka.y,  ka.z,  ka.w,  kb.x,  kb.y,  kb.z,  kb.w};

        #pragma unroll
        for (int u = 0; u < 8; u++) {
            float d0 = va[u].x - vb[u].x;
            float d1 = va[u].y - vb[u].y;
            float d2 = va[u].z - vb[u].z;
            float qq = fmaf(d0, d0, fmaf(d1, d1, d2 * d2));
            float l  = sqrtf(qq + EPS);
            float dl = l - l0v[u];
            term = fmaf(0.5f * kv[u], dl * dl, term);
        }
    } else {
        for (long long e = base; e < E; e++) {
            int i = __ldg(indices + 2 * e);
            int j = __ldg(indices + 2 * e + 1);
            float4 a = __ldg(&g_x4[i]);
            float4 b = __ldg(&g_x4[j]);
            float d0 = a.x - b.x, d1 = a.y - b.y, d2 = a.z - b.z;
            float qq = fmaf(d0, d0, fmaf(d1, d1, d2 * d2));
            float l  = sqrtf(qq + EPS);
            float dl = l - __ldg(l0 + e);
            term = fmaf(0.5f * __ldg(k + e), dl * dl, term);
        }
    }

    // Warp reduction
    #pragma unroll
    for (int off = 16; off > 0; off >>= 1)
        term += __shfl_down_sync(0xFFFFFFFFu, term, off);

    // Block reduction
    __shared__ float warp_sums[8];
    int lane = threadIdx.x & 31;
    int wid  = threadIdx.x >> 5;
    if (lane == 0) warp_sums[wid] = term;
    __syncthreads();

    if (wid == 0) {
        float v = (lane < 8) ? warp_sums[lane] : 0.0f;
        #pragma unroll
        for (int off = 4; off > 0; off >>= 1)
            v += __shfl_down_sync(0xFFFFFFFFu, v, off);
        if (lane == 0) {
            unsigned long long add =
                (unsigned long long)((double)v * FP_SCALE + 0.5) + COUNT_ONE;
            unsigned long long old = atomicAdd(&g_packed_acc, add);
            unsigned long long now = old + add;
            if ((now >> 48) == (unsigned long long)gridDim.x) {
                out[0] = (float)((double)(now & SUM_MASK) / FP_SCALE);
            }
        }
    }
}

// ---- Fallback path (V > MAX_V) ----
__global__ void zero_acc_kernel() { g_energy_acc = 0.0; }

__global__ void __launch_bounds__(256)
spring_energy_fallback_kernel(const float* __restrict__ x,
                              const int2* __restrict__ indices,
                              const float* __restrict__ l0,
                              const float* __restrict__ k,
                              long long E)
{
    long long e = (long long)blockIdx.x * blockDim.x + threadIdx.x;
    float term = 0.0f;
    if (e < E) {
        int2 ij = __ldg(indices + e);
        const float* xi = x + 3LL * ij.x;
        const float* xj = x + 3LL * ij.y;
        float d0 = __ldg(xi + 0) - __ldg(xj + 0);
        float d1 = __ldg(xi + 1) - __ldg(xj + 1);
        float d2 = __ldg(xi + 2) - __ldg(xj + 2);
        float q = fmaf(d0, d0, fmaf(d1, d1, d2 * d2));
        float l = sqrtf(q + EPS);
        float dl = l - __ldg(l0 + e);
        term = 0.5f * __ldg(k + e) * dl * dl;
    }
    #pragma unroll
    for (int off = 16; off > 0; off >>= 1)
        term += __shfl_down_sync(0xFFFFFFFFu, term, off);
    __shared__ float warp_sums[8];
    int lane = threadIdx.x & 31;
    int wid  = threadIdx.x >> 5;
    if (lane == 0) warp_sums[wid] = term;
    __syncthreads();
    if (wid == 0) {
        float v = (lane < 8) ? warp_sums[lane] : 0.0f;
        #pragma unroll
        for (int off = 4; off > 0; off >>= 1)
            v += __shfl_down_sync(0xFFFFFFFFu, v, off);
        if (lane == 0)
            atomicAdd(&g_energy_acc, (double)v);
    }
}

__global__ void finalize_kernel(float* out) {
    out[0] = (float)g_energy_acc;
}

extern "C" void kernel_launch(void* const* d_in, const int* in_sizes, int n_in,
                              void* d_out, int out_size)
{
    const float* x       = (const float*)d_in[0];
    const int*   indices = (const int*)d_in[1];
    const float* l0      = (const float*)d_in[2];
    const float* k       = (const float*)d_in[3];
    float*       out     = (float*)d_out;

    int       V = in_sizes[0] / 3;
    long long E = (long long)in_sizes[2];

    if (V <= MAX_V) {
        int vblocks = (V + 255) / 256;
        repack_kernel<<<vblocks, 256>>>(x, V);
        const int threads = 256;
        long long eblocks = (E + 8LL * threads - 1) / (8LL * threads);
        spring_energy_kernel<<<(unsigned)eblocks, threads>>>(indices, l0, k, E, out);
    } else {
        zero_acc_kernel<<<1, 1>>>();
        long long eblocks = (E + 255) / 256;
        spring_energy_fallback_kernel<<<(unsigned)eblocks, 256>>>(
            x, (const int2*)indices, l0, k, E);
        finalize_kernel<<<1, 1>>>(out);
    }
}

// round 10
// speedup vs baseline: 1.0805x; 1.0805x over previous
#include <cuda_runtime.h>
#include <cstdint>

#define EPS 1e-06f
#define MAX_V 2000000

#define FP_SCALE   65536.0
#define COUNT_ONE  (1ULL << 48)
#define SUM_MASK   (COUNT_ONE - 1ULL)

__device__ float4 g_x4[MAX_V];
__device__ unsigned long long g_packed_acc;
__device__ double g_energy_acc;   // fallback path only

__global__ void __launch_bounds__(256)
repack_kernel(const float* __restrict__ x, int V)
{
    int v = blockIdx.x * blockDim.x + threadIdx.x;
    if (v == 0) {
        g_packed_acc = 0ULL;
        g_energy_acc = 0.0;
    }
    if (v < V) {
        float a = __ldg(x + 3 * v + 0);
        float b = __ldg(x + 3 * v + 1);
        float c = __ldg(x + 3 * v + 2);
        g_x4[v] = make_float4(a, b, c, 0.0f);
    }
}

// 4 edges per thread, 128-thread blocks: 46 regs -> 11 blocks/SM -> 44 warps,
// ~352 in-flight gathers per SM.
__global__ void __launch_bounds__(128)
spring_energy_kernel(const int* __restrict__ indices,  // [E*2] int32
                     const float* __restrict__ l0,
                     const float* __restrict__ k,
                     long long E,
                     float* __restrict__ out)
{
    long long t    = (long long)blockIdx.x * blockDim.x + threadIdx.x;
    long long base = 4 * t;

    float term = 0.0f;
    if (base + 3 < E) {
        int4 p = __ldg((const int4*)(indices + 2 * base));
        int4 q = __ldg((const int4*)(indices + 2 * base) + 1);
        float4 l04 = __ldg((const float4*)(l0 + base));
        float4 k4  = __ldg((const float4*)(k  + base));

        float4 a0 = __ldg(&g_x4[p.x]);
        float4 b0 = __ldg(&g_x4[p.y]);
        float4 a1 = __ldg(&g_x4[p.z]);
        float4 b1 = __ldg(&g_x4[p.w]);
        float4 a2 = __ldg(&g_x4[q.x]);
        float4 b2 = __ldg(&g_x4[q.y]);
        float4 a3 = __ldg(&g_x4[q.z]);
        float4 b3 = __ldg(&g_x4[q.w]);

        float d0, d1, d2, qq, l, dl;

        d0 = a0.x - b0.x; d1 = a0.y - b0.y; d2 = a0.z - b0.z;
        qq = fmaf(d0, d0, fmaf(d1, d1, d2 * d2));
        l  = sqrtf(qq + EPS); dl = l - l04.x;
        term = fmaf(0.5f * k4.x, dl * dl, term);

        d0 = a1.x - b1.x; d1 = a1.y - b1.y; d2 = a1.z - b1.z;
        qq = fmaf(d0, d0, fmaf(d1, d1, d2 * d2));
        l  = sqrtf(qq + EPS); dl = l - l04.y;
        term = fmaf(0.5f * k4.y, dl * dl, term);

        d0 = a2.x - b2.x; d1 = a2.y - b2.y; d2 = a2.z - b2.z;
        qq = fmaf(d0, d0, fmaf(d1, d1, d2 * d2));
        l  = sqrtf(qq + EPS); dl = l - l04.z;
        term = fmaf(0.5f * k4.z, dl * dl, term);

        d0 = a3.x - b3.x; d1 = a3.y - b3.y; d2 = a3.z - b3.z;
        qq = fmaf(d0, d0, fmaf(d1, d1, d2 * d2));
        l  = sqrtf(qq + EPS); dl = l - l04.w;
        term = fmaf(0.5f * k4.w, dl * dl, term);
    } else {
        for (long long e = base; e < E; e++) {
            int i = __ldg(indices + 2 * e);
            int j = __ldg(indices + 2 * e + 1);
            float4 a = __ldg(&g_x4[i]);
            float4 b = __ldg(&g_x4[j]);
            float d0 = a.x - b.x, d1 = a.y - b.y, d2 = a.z - b.z;
            float qq = fmaf(d0, d0, fmaf(d1, d1, d2 * d2));
            float l  = sqrtf(qq + EPS);
            float dl = l - __ldg(l0 + e);
            term = fmaf(0.5f * __ldg(k + e), dl * dl, term);
        }
    }

    // Warp reduction
    #pragma unroll
    for (int off = 16; off > 0; off >>= 1)
        term += __shfl_down_sync(0xFFFFFFFFu, term, off);

    // Block reduction (4 warps)
    __shared__ float warp_sums[4];
    int lane = threadIdx.x & 31;
    int wid  = threadIdx.x >> 5;
    if (lane == 0) warp_sums[wid] = term;
    __syncthreads();

    if (wid == 0) {
        float v = (lane < 4) ? warp_sums[lane] : 0.0f;
        #pragma unroll
        for (int off = 2; off > 0; off >>= 1)
            v += __shfl_down_sync(0xFFFFFFFFu, v, off);
        if (lane == 0) {
            unsigned long long add =
                (unsigned long long)((double)v * FP_SCALE + 0.5) + COUNT_ONE;
            unsigned long long old = atomicAdd(&g_packed_acc, add);
            unsigned long long now = old + add;
            if ((now >> 48) == (unsigned long long)gridDim.x) {
                out[0] = (float)((double)(now & SUM_MASK) / FP_SCALE);
            }
        }
    }
}

// ---- Fallback path (V > MAX_V) ----
__global__ void zero_acc_kernel() { g_energy_acc = 0.0; }

__global__ void __launch_bounds__(256)
spring_energy_fallback_kernel(const float* __restrict__ x,
                              const int2* __restrict__ indices,
                              const float* __restrict__ l0,
                              const float* __restrict__ k,
                              long long E)
{
    long long e = (long long)blockIdx.x * blockDim.x + threadIdx.x;
    float term = 0.0f;
    if (e < E) {
        int2 ij = __ldg(indices + e);
        const float* xi = x + 3LL * ij.x;
        const float* xj = x + 3LL * ij.y;
        float d0 = __ldg(xi + 0) - __ldg(xj + 0);
        float d1 = __ldg(xi + 1) - __ldg(xj + 1);
        float d2 = __ldg(xi + 2) - __ldg(xj + 2);
        float q = fmaf(d0, d0, fmaf(d1, d1, d2 * d2));
        float l = sqrtf(q + EPS);
        float dl = l - __ldg(l0 + e);
        term = 0.5f * __ldg(k + e) * dl * dl;
    }
    #pragma unroll
    for (int off = 16; off > 0; off >>= 1)
        term += __shfl_down_sync(0xFFFFFFFFu, term, off);
    __shared__ float warp_sums[8];
    int lane = threadIdx.x & 31;
    int wid  = threadIdx.x >> 5;
    if (lane == 0) warp_sums[wid] = term;
    __syncthreads();
    if (wid == 0) {
        float v = (lane < 8) ? warp_sums[lane] : 0.0f;
        #pragma unroll
        for (int off = 4; off > 0; off >>= 1)
            v += __shfl_down_sync(0xFFFFFFFFu, v, off);
        if (lane == 0)
            atomicAdd(&g_energy_acc, (double)v);
    }
}

__global__ void finalize_kernel(float* out) {
    out[0] = (float)g_energy_acc;
}

extern "C" void kernel_launch(void* const* d_in, const int* in_sizes, int n_in,
                              void* d_out, int out_size)
{
    const float* x       = (const float*)d_in[0];
    const int*   indices = (const int*)d_in[1];
    const float* l0      = (const float*)d_in[2];
    const float* k       = (const float*)d_in[3];
    float*       out     = (float*)d_out;

    int       V = in_sizes[0] / 3;
    long long E = (long long)in_sizes[2];

    if (V <= MAX_V) {
        int vblocks = (V + 255) / 256;
        repack_kernel<<<vblocks, 256>>>(x, V);
        const int threads = 128;
        long long eblocks = (E + 4LL * threads - 1) / (4LL * threads);
        spring_energy_kernel<<<(unsigned)eblocks, threads>>>(indices, l0, k, E, out);
    } else {
        zero_acc_kernel<<<1, 1>>>();
        long long eblocks = (E + 255) / 256;
        spring_energy_fallback_kernel<<<(unsigned)eblocks, 256>>>(
            x, (const int2*)indices, l0, k, E);
        finalize_kernel<<<1, 1>>>(out);
    }
}